// round 16
// baseline (speedup 1.0000x reference)
#include <cuda_runtime.h>
#include <cuda_bf16.h>
#include <vector>
#include <cmath>
#include <cstring>

#define HID 256
#define OLEN 192
#define NMODE 32
#define TSUM 1344
#define NCOL 12288   // 192*32*2
#define NH4 (84 * 16 * 32)      // H-frag uint4 count
#define NE4 (3 * 12 * 16 * 32)  // em-frag uint4 count

// ---------------- host constant tables ----------------
static float h_H[TSUM * HID];
static float h_em[3 * OLEN * HID];
static float h_al[3 * NMODE * 2];
static unsigned h_HfH[NH4 * 4], h_HfL[NH4 * 4];
static unsigned h_EfH[NE4 * 4], h_EfL[NE4 * 4];

static inline unsigned short f2bf(float x) {
  unsigned u; memcpy(&u, &x, 4);
  return (unsigned short)((u + 0x7FFF + ((u >> 16) & 1)) >> 16);
}
static inline float bff(unsigned short b) {
  unsigned u = (unsigned)b << 16; float f; memcpy(&f, &u, 4); return f;
}
static inline void pack_pair(float e0, float e1, unsigned& hi, unsigned& lo) {
  unsigned short h0 = f2bf(e0), h1 = f2bf(e1);
  unsigned short l0 = f2bf(e0 - bff(h0)), l1 = f2bf(e1 - bff(h1));
  hi = ((unsigned)h1 << 16) | h0;
  lo = ((unsigned)l1 << 16) | l0;
}

struct HostInit {
  HostInit() {
    const double PI2 = 6.283185307179586476925286766559;
    for (int si = 0; si < 3; si++) {
      int sc = 1 << si;
      int T = OLEN * sc;
      int uoff = (si == 0) ? 0 : (si == 1) ? 192 : 576;
      double dt = 1.0 / (double)T;
      std::vector<double> M((size_t)HID * HID), R((size_t)HID * (HID + 1)), X((size_t)HID * (HID + 1));
      for (int r = 0; r < HID; r++) {
        for (int c = 0; c < HID; c++) {
          double a = (r < c) ? -1.0 : (((r - c) & 1) ? 1.0 : -1.0);
          a *= (2.0 * r + 1.0);
          M[(size_t)r * HID + c] = (r == c ? 1.0 : 0.0) - 0.5 * dt * a;
          R[(size_t)r * (HID + 1) + c] = (r == c ? 1.0 : 0.0) + 0.5 * dt * a;
        }
        R[(size_t)r * (HID + 1) + HID] = ((r & 1) ? -1.0 : 1.0) * (2.0 * r + 1.0) * dt;
      }
      for (int col = 0; col < HID; col++) {
        int piv = col; double mx = fabs(M[(size_t)col * HID + col]);
        for (int r = col + 1; r < HID; r++) { double v = fabs(M[(size_t)r * HID + col]); if (v > mx) { mx = v; piv = r; } }
        if (piv != col) {
          for (int c = col; c < HID; c++) { double t = M[(size_t)col*HID+c]; M[(size_t)col*HID+c] = M[(size_t)piv*HID+c]; M[(size_t)piv*HID+c] = t; }
          for (int c = 0; c <= HID; c++) { double t = R[(size_t)col*(HID+1)+c]; R[(size_t)col*(HID+1)+c] = R[(size_t)piv*(HID+1)+c]; R[(size_t)piv*(HID+1)+c] = t; }
        }
        double d = M[(size_t)col * HID + col];
        for (int r = col + 1; r < HID; r++) {
          double f = M[(size_t)r * HID + col] / d;
          if (f != 0.0) {
            for (int c = col; c < HID; c++) M[(size_t)r*HID+c] -= f * M[(size_t)col*HID+c];
            for (int c = 0; c <= HID; c++) R[(size_t)r*(HID+1)+c] -= f * R[(size_t)col*(HID+1)+c];
          }
        }
      }
      for (int r = HID - 1; r >= 0; r--) {
        double diag = M[(size_t)r * HID + r];
        for (int c = 0; c <= HID; c++) {
          double s = R[(size_t)r * (HID + 1) + c];
          for (int rr = r + 1; rr < HID; rr++) s -= M[(size_t)r*HID+rr] * X[(size_t)rr*(HID+1)+c];
          X[(size_t)r * (HID + 1) + c] = s / diag;
        }
      }
      std::vector<double> Ad((size_t)HID * HID), h(HID), hn(HID);
      for (int r = 0; r < HID; r++) {
        for (int c = 0; c < HID; c++) Ad[(size_t)r*HID+c] = (double)(float)X[(size_t)r*(HID+1)+c];
        h[r] = (double)(float)X[(size_t)r*(HID+1)+HID];
      }
      for (int u = 0; u < T; u++) {
        for (int i = 0; i < HID; i++) h_H[(size_t)(uoff + u) * HID + i] = (float)h[i];
        for (int i = 0; i < HID; i++) {
          double s = 0; const double* row = &Ad[(size_t)i * HID];
          for (int j = 0; j < HID; j++) s += row[j] * h[j];
          hn[i] = s;
        }
        h.swap(hn);
      }
      for (int t = 0; t < OLEN; t++) {
        int j = T - OLEN + t;
        double x = 1.0 - 2.0 * ((double)j * dt);
        float* dst = &h_em[((size_t)si * OLEN + t) * HID];
        double p0 = 1.0, p1 = x;
        dst[0] = (float)p0; dst[1] = (float)p1;
        for (int n = 1; n < HID - 1; n++) {
          double p2 = ((2.0*n+1.0)*x*p1 - (double)n*p0) / (double)(n+1);
          dst[n+1] = (float)p2; p0 = p1; p1 = p2;
        }
      }
      h_al[(si * NMODE + 0) * 2 + 0] = (float)(1.0 / (double)T);
      h_al[(si * NMODE + 0) * 2 + 1] = 0.0f;
      for (int k = 1; k < NMODE; k++) {
        double th = PI2 * (double)(191 * k) / (double)T;
        h_al[(si * NMODE + k) * 2 + 0] = (float)(2.0 / T * cos(th));
        h_al[(si * NMODE + k) * 2 + 1] = (float)(2.0 / T * sin(th));
      }
    }
    for (int ut = 0; ut < 84; ut++)
      for (int mmg = 0; mmg < 16; mmg++)
        for (int lane = 0; lane < 32; lane++) {
          int r = lane >> 2, c = lane & 3;
          int r0 = ut * 16 + r, r1 = r0 + 8, i0 = mmg * 16;
          int idx = (((ut * 16) + mmg) * 32 + lane) * 4;
          pack_pair(h_H[(size_t)r0*256 + i0+2*c],   h_H[(size_t)r0*256 + i0+2*c+1], h_HfH[idx+0], h_HfL[idx+0]);
          pack_pair(h_H[(size_t)r1*256 + i0+2*c],   h_H[(size_t)r1*256 + i0+2*c+1], h_HfH[idx+1], h_HfL[idx+1]);
          pack_pair(h_H[(size_t)r0*256 + i0+2*c+8], h_H[(size_t)r0*256 + i0+2*c+9], h_HfH[idx+2], h_HfL[idx+2]);
          pack_pair(h_H[(size_t)r1*256 + i0+2*c+8], h_H[(size_t)r1*256 + i0+2*c+9], h_HfH[idx+3], h_HfL[idx+3]);
        }
    for (int s = 0; s < 3; s++)
      for (int mt = 0; mt < 12; mt++)
        for (int mmg = 0; mmg < 16; mmg++)
          for (int lane = 0; lane < 32; lane++) {
            int r = lane >> 2, c = lane & 3;
            int r0 = mt * 16 + r, r1 = r0 + 8, o0 = mmg * 16;
            const float* A = h_em + (size_t)s * 192 * 256;
            int idx = ((((s * 12 + mt) * 16) + mmg) * 32 + lane) * 4;
            pack_pair(A[(size_t)r0*256 + o0+2*c],   A[(size_t)r0*256 + o0+2*c+1], h_EfH[idx+0], h_EfL[idx+0]);
            pack_pair(A[(size_t)r1*256 + o0+2*c],   A[(size_t)r1*256 + o0+2*c+1], h_EfH[idx+1], h_EfL[idx+1]);
            pack_pair(A[(size_t)r0*256 + o0+2*c+8], A[(size_t)r0*256 + o0+2*c+9], h_EfH[idx+2], h_EfL[idx+2]);
            pack_pair(A[(size_t)r1*256 + o0+2*c+8], A[(size_t)r1*256 + o0+2*c+9], h_EfH[idx+3], h_EfL[idx+3]);
          }
  }
};
static HostInit g_init;

// ---------------- device scratch ----------------
__device__ uint4 d_HfH[NH4], d_HfL[NH4];
__device__ uint4 d_EfH[NE4], d_EfL[NE4];
__device__ __nv_bfloat16 d_W2h[3 * 256 * NCOL];
__device__ __nv_bfloat16 d_W2l[3 * 256 * NCOL];
__device__ float d_Bs[7 * 192 * 32 * 2];
__device__ int d_flag[7 * 192];
__device__ float d_G[TSUM * 192];
__device__ float d_P[8 * 98304];
__device__ float d_ald[3 * 32 * 2];

__device__ __forceinline__ void mma16(float4& d, const uint4& a, unsigned b0, unsigned b1) {
  asm("mma.sync.aligned.m16n8k16.row.col.f32.bf16.bf16.f32 "
      "{%0,%1,%2,%3},{%4,%5,%6,%7},{%8,%9},{%0,%1,%2,%3};"
      : "+f"(d.x), "+f"(d.y), "+f"(d.z), "+f"(d.w)
      : "r"(a.x), "r"(a.y), "r"(a.z), "r"(a.w), "r"(b0), "r"(b1));
}

__device__ __forceinline__ unsigned pkbf(float a, float b) {
  __nv_bfloat16 ha = __float2bfloat16_rn(a), hb = __float2bfloat16_rn(b);
  return ((unsigned)__bfloat16_as_ushort(hb) << 16) | __bfloat16_as_ushort(ha);
}

__device__ __forceinline__ float scan_r(float v, int r) {
  float t;
  t = __shfl_up_sync(0xffffffffu, v, 4);  v += (r >= 1) ? t : 0.f;
  t = __shfl_up_sync(0xffffffffu, v, 8);  v += (r >= 2) ? t : 0.f;
  t = __shfl_up_sync(0xffffffffu, v, 16); v += (r >= 4) ? t : 0.f;
  return v;
}

// K0: pull host constants via ATS (GB300 C2C); zero lookback flags
__global__ void k_copy(const float* __restrict__ hal,
                       const uint4* __restrict__ hHfH, const uint4* __restrict__ hHfL,
                       const uint4* __restrict__ hEfH, const uint4* __restrict__ hEfL) {
  int i = blockIdx.x * blockDim.x + threadIdx.x, st = gridDim.x * blockDim.x;
  for (int j = i; j < 7 * 192; j += st) d_flag[j] = 0;
  for (int j = i; j < 3 * 32 * 2; j += st) d_ald[j] = hal[j];
  for (int j = i; j < NH4; j += st) { d_HfH[j] = hHfH[j]; d_HfL[j] = hHfL[j]; }
  for (int j = i; j < NE4; j += st) { d_EfH[j] = hEfH[j]; d_EfL[j] = hEfL[j]; }
}

// K1: W2 = alpha .* (em @ Wc). bf16 3-pass, double-buffered, 2 blocks/SM.
__global__ void __launch_bounds__(256, 2) k_w2(const float* __restrict__ wr, const float* __restrict__ wi) {
  __shared__ unsigned Bph[2][16 * 72], Bpl[2][16 * 72];
  int s = blockIdx.y, i = blockIdx.x;
  int tid = threadIdx.x, wid = tid >> 5, lane = tid & 31;
  int whalf = wid & 1, wg = wid >> 1;
  int r = lane >> 2, c = lane & 3;
  const float* wrb = wr + (size_t)(s * 256 + i) * 8192;
  const float* wib = wi + (size_t)(s * 256 + i) * 8192;
  float4 acc[3][4];
#pragma unroll
  for (int mt = 0; mt < 3; mt++)
#pragma unroll
    for (int j = 0; j < 4; j++) acc[mt][j] = make_float4(0.f, 0.f, 0.f, 0.f);
  int o2s = tid >> 4, kp = tid & 15;

  float2 ra, rb, ia, ib;
  {
    int oa = 2 * o2s;
    ra = *(const float2*)(wrb + (size_t)oa * 32 + 2 * kp);
    rb = *(const float2*)(wrb + (size_t)(oa + 1) * 32 + 2 * kp);
    ia = *(const float2*)(wib + (size_t)oa * 32 + 2 * kp);
    ib = *(const float2*)(wib + (size_t)(oa + 1) * 32 + 2 * kp);
  }
  for (int ch = 0; ch < 8; ch++) {
    int bsel = ch & 1;
    {
      float va[4] = {ra.x, ia.x, ra.y, ia.y};
      float vb[4] = {rb.x, ib.x, rb.y, ib.y};
#pragma unroll
      for (int e = 0; e < 4; e++) {
        int n = 4 * kp + e;
        int p = o2s * 72 + (n & 7) * 8 + (n >> 3);
        __nv_bfloat16 ha = __float2bfloat16_rn(va[e]), hb = __float2bfloat16_rn(vb[e]);
        Bph[bsel][p] = ((unsigned)__bfloat16_as_ushort(hb) << 16) | __bfloat16_as_ushort(ha);
        Bpl[bsel][p] = pkbf(va[e] - __bfloat162float(ha), vb[e] - __bfloat162float(hb));
      }
    }
    __syncthreads();
    if (ch < 7) {
      int oa = (ch + 1) * 32 + 2 * o2s;
      ra = *(const float2*)(wrb + (size_t)oa * 32 + 2 * kp);
      rb = *(const float2*)(wrb + (size_t)(oa + 1) * 32 + 2 * kp);
      ia = *(const float2*)(wib + (size_t)oa * 32 + 2 * kp);
      ib = *(const float2*)(wib + (size_t)(oa + 1) * 32 + 2 * kp);
    }
#pragma unroll
    for (int m = 0; m < 2; m++) {
      uint4 b0h = *(const uint4*)&Bph[bsel][(8 * m + c) * 72 + r * 8 + whalf * 4];
      uint4 b1h = *(const uint4*)&Bph[bsel][(8 * m + c + 4) * 72 + r * 8 + whalf * 4];
      uint4 b0l = *(const uint4*)&Bpl[bsel][(8 * m + c) * 72 + r * 8 + whalf * 4];
      uint4 b1l = *(const uint4*)&Bpl[bsel][(8 * m + c + 4) * 72 + r * 8 + whalf * 4];
      const unsigned* p0h = (const unsigned*)&b0h;
      const unsigned* p1h = (const unsigned*)&b1h;
      const unsigned* p0l = (const unsigned*)&b0l;
      const unsigned* p1l = (const unsigned*)&b1l;
      int mmg = ch * 2 + m;
#pragma unroll
      for (int mt = 0; mt < 3; mt++) {
        int mtile = wg * 3 + mt;
        uint4 ah = d_EfH[((s * 12 + mtile) * 16 + mmg) * 32 + lane];
        uint4 al = d_EfL[((s * 12 + mtile) * 16 + mmg) * 32 + lane];
#pragma unroll
        for (int j = 0; j < 4; j++) {
          mma16(acc[mt][j], ah, p0h[j], p1h[j]);
          mma16(acc[mt][j], ah, p0l[j], p1l[j]);
          mma16(acc[mt][j], al, p0h[j], p1h[j]);
        }
      }
    }
  }
  size_t base0 = (size_t)(s * 256 + i) * NCOL;
#pragma unroll
  for (int mt = 0; mt < 3; mt++) {
#pragma unroll
    for (int j = 0; j < 4; j++) {
      int ncol = whalf * 32 + j * 8 + 2 * c;
      int kmode = ncol >> 1;
      float alr = d_ald[(s * 32 + kmode) * 2], ali = d_ald[(s * 32 + kmode) * 2 + 1];
      float4 cv = acc[mt][j];
      int t0 = wg * 48 + mt * 16 + r;
      float re0 = alr * cv.x - ali * cv.y, im0 = alr * cv.y + ali * cv.x;
      float re1 = alr * cv.z - ali * cv.w, im1 = alr * cv.w + ali * cv.z;
      size_t e0 = base0 + (size_t)t0 * 64 + ncol;
      size_t e1 = base0 + (size_t)(t0 + 8) * 64 + ncol;
      __nv_bfloat16 h0r = __float2bfloat16_rn(re0), h0i = __float2bfloat16_rn(im0);
      __nv_bfloat16 h1r = __float2bfloat16_rn(re1), h1i = __float2bfloat16_rn(im1);
      *(unsigned*)(d_W2h + e0) = ((unsigned)__bfloat16_as_ushort(h0i) << 16) | __bfloat16_as_ushort(h0r);
      *(unsigned*)(d_W2h + e1) = ((unsigned)__bfloat16_as_ushort(h1i) << 16) | __bfloat16_as_ushort(h1r);
      *(unsigned*)(d_W2l + e0) = pkbf(re0 - __bfloat162float(h0r), im0 - __bfloat162float(h0i));
      *(unsigned*)(d_W2l + e1) = pkbf(re1 - __bfloat162float(h1r), im1 - __bfloat162float(h1i));
    }
  }
}

// K2: fused GEMM + scan + k-reduction with cross-chunk lookback.
__global__ void k_gemmU() {
  __shared__ unsigned Bph[2][16 * 72], Bpl[2][16 * 72];
  __shared__ float WsRe[12][32], WsIm[12][32];
  int bn = blockIdx.x, ub = blockIdx.y;
  int s = (ub == 0) ? 0 : (ub < 3) ? 1 : 2;
  int tid = threadIdx.x, wid = tid >> 5, lane = tid & 31;
  int r = lane >> 2, c = lane & 3;
  int ut = ub * 12 + wid;
  float4 acc[8];
#pragma unroll
  for (int j = 0; j < 8; j++) acc[j] = make_float4(0.f, 0.f, 0.f, 0.f);

  int pairsel = tid >> 7, t2 = tid & 127;
  int k2 = t2 >> 3, oc = t2 & 7;
  const __nv_bfloat16* bbase = pairsel ? d_W2l : d_W2h;
  uint4 va, vb;
  if (tid < 256) {
    const __nv_bfloat16* src = bbase + (size_t)(s * 256 + 2 * k2) * NCOL + bn * 64 + oc * 8;
    va = *(const uint4*)src;
    vb = *(const uint4*)(src + NCOL);
  }
  for (int ch = 0; ch < 8; ch++) {
    int bsel = ch & 1;
    if (tid < 256) {
      unsigned* dst = pairsel ? Bpl[bsel] : Bph[bsel];
      const unsigned* pa = (const unsigned*)&va;
      const unsigned* pb = (const unsigned*)&vb;
#pragma unroll
      for (int h2 = 0; h2 < 4; h2++) {
        int n0 = oc * 8 + h2 * 2, n1 = n0 + 1;
        dst[k2 * 72 + (n0 & 7) * 8 + (n0 >> 3)] = __byte_perm(pa[h2], pb[h2], 0x5410);
        dst[k2 * 72 + (n1 & 7) * 8 + (n1 >> 3)] = __byte_perm(pa[h2], pb[h2], 0x7632);
      }
    }
    __syncthreads();
    if (ch < 7 && tid < 256) {
      const __nv_bfloat16* src = bbase + (size_t)(s * 256 + (ch + 1) * 32 + 2 * k2) * NCOL + bn * 64 + oc * 8;
      va = *(const uint4*)src;
      vb = *(const uint4*)(src + NCOL);
    }
#pragma unroll
    for (int m = 0; m < 2; m++) {
      int mmg = ch * 2 + m;
      uint4 ah = d_HfH[(ut * 16 + mmg) * 32 + lane];
      uint4 al = d_HfL[(ut * 16 + mmg) * 32 + lane];
#pragma unroll
      for (int half = 0; half < 2; half++) {
        uint4 b0h = *(const uint4*)&Bph[bsel][(8 * m + c) * 72 + r * 8 + half * 4];
        uint4 b1h = *(const uint4*)&Bph[bsel][(8 * m + c + 4) * 72 + r * 8 + half * 4];
        uint4 b0l = *(const uint4*)&Bpl[bsel][(8 * m + c) * 72 + r * 8 + half * 4];
        uint4 b1l = *(const uint4*)&Bpl[bsel][(8 * m + c + 4) * 72 + r * 8 + half * 4];
        const unsigned* p0h = (const unsigned*)&b0h;
        const unsigned* p1h = (const unsigned*)&b1h;
        const unsigned* p0l = (const unsigned*)&b0l;
        const unsigned* p1l = (const unsigned*)&b1l;
#pragma unroll
        for (int j = 0; j < 4; j++) {
          int jj = half * 4 + j;
          mma16(acc[jj], ah, p0h[j], p1h[j]);
          mma16(acc[jj], ah, p0l[j], p1l[j]);
          mma16(acc[jj], al, p0h[j], p1h[j]);
        }
      }
    }
  }
  // ---------- fused scan epilogue (angle-addition recurrence) ----------
  int T = 192 << s;
  int uoff = (s == 0) ? 0 : (s == 1) ? 192 : 576;
  int ul0 = ub * 192 - uoff + wid * 16;
  float pi2t = 6.2831853071795864f / (float)T;
  int u0 = ul0 + r, u1 = u0 + 8;
  float cu0, su0, cu1, su1, cs0, ss0, cs1, ss1;
  __sincosf(pi2t * (float)((u0 * c) % T), &su0, &cu0);
  __sincosf(pi2t * (float)((u1 * c) % T), &su1, &cu1);
  __sincosf(pi2t * (float)((4 * u0) % T), &ss0, &cs0);
  __sincosf(pi2t * (float)((4 * u1) % T), &ss1, &cs1);
#pragma unroll
  for (int j = 0; j < 8; j++) {
    float re0 = cu0 * acc[j].x + su0 * acc[j].y;
    float im0 = cu0 * acc[j].y - su0 * acc[j].x;
    float re1 = cu1 * acc[j].z + su1 * acc[j].w;
    float im1 = cu1 * acc[j].w - su1 * acc[j].z;
    acc[j].x = re0; acc[j].y = im0; acc[j].z = re1; acc[j].w = im1;
    float t0 = cu0 * cs0 - su0 * ss0; su0 = su0 * cs0 + cu0 * ss0; cu0 = t0;
    float t1 = cu1 * cs1 - su1 * ss1; su1 = su1 * cs1 + cu1 * ss1; cu1 = t1;
  }
#pragma unroll
  for (int j = 0; j < 8; j++) {
    acc[j].x = scan_r(acc[j].x, r);
    acc[j].y = scan_r(acc[j].y, r);
    float t0re = __shfl_sync(0xffffffffu, acc[j].x, 28 + c);
    float t0im = __shfl_sync(0xffffffffu, acc[j].y, 28 + c);
    acc[j].z = scan_r(acc[j].z, r) + t0re;
    acc[j].w = scan_r(acc[j].w, r) + t0im;
  }
  if (r == 7) {
#pragma unroll
    for (int j = 0; j < 8; j++) { WsRe[wid][j * 4 + c] = acc[j].z; WsIm[wid][j * 4 + c] = acc[j].w; }
  }
  __syncthreads();
  if (wid == 0) {
    float runr = 0.f, runi = 0.f;
#pragma unroll
    for (int w = 0; w < 12; w++) {
      float tr = WsRe[w][lane], ti = WsIm[w][lane];
      WsRe[w][lane] = runr; WsIm[w][lane] = runi;
      runr += tr; runi += ti;
    }
    ((float2*)d_Bs)[(ub * 192 + bn) * 32 + lane] = make_float2(runr, runi);
    __threadfence();
    __syncwarp();
    if (lane == 0) atomicExch(&d_flag[ub * 192 + bn], 1);
    int ubbase = (s == 0) ? 0 : (s == 1) ? 1 : 3;
    if (ub > ubbase) {
      float sr = 0.f, si = 0.f;
      for (int p = ubbase; p < ub; p++) {
        if (lane == 0) { while (atomicAdd(&d_flag[p * 192 + bn], 0) == 0) {} }
        __syncwarp();
        __threadfence();
        float2 v = ((const float2*)d_Bs)[(p * 192 + bn) * 32 + lane];
        sr += v.x; si += v.y;
      }
#pragma unroll
      for (int w = 0; w < 12; w++) { WsRe[w][lane] += sr; WsIm[w][lane] += si; }
    }
  }
  __syncthreads();
  int m0 = ul0 + r, m1 = m0 + 8;
  int tau0 = T - 1 - m0, tau1 = T - 1 - m1;
  float ca0, sa0, ca1, sa1, cS0, sS0, cS1, sS1;
  __sincosf(pi2t * (float)((tau0 * c) % T), &sa0, &ca0);
  __sincosf(pi2t * (float)((tau1 * c) % T), &sa1, &ca1);
  __sincosf(pi2t * (float)((4 * tau0) % T), &sS0, &cS0);
  __sincosf(pi2t * (float)((4 * tau1) % T), &sS1, &cS1);
  float g0 = 0.f, g1 = 0.f;
#pragma unroll
  for (int j = 0; j < 8; j++) {
    int k = j * 4 + c;
    float wre = WsRe[wid][k], wim = WsIm[wid][k];
    float pre0 = acc[j].x + wre, pim0 = acc[j].y + wim;
    float pre1 = acc[j].z + wre, pim1 = acc[j].w + wim;
    g0 += ca0 * pre0 + sa0 * pim0;
    g1 += ca1 * pre1 + sa1 * pim1;
    float t0 = ca0 * cS0 - sa0 * sS0; sa0 = sa0 * cS0 + ca0 * sS0; ca0 = t0;
    float t1 = ca1 * cS1 - sa1 * sS1; sa1 = sa1 * cS1 + ca1 * sS1; ca1 = t1;
  }
  g0 += __shfl_xor_sync(0xffffffffu, g0, 1);
  g0 += __shfl_xor_sync(0xffffffffu, g0, 2);
  g1 += __shfl_xor_sync(0xffffffffu, g1, 1);
  g1 += __shfl_xor_sync(0xffffffffu, g1, 2);
  if (c == 0) {
    d_G[(size_t)(uoff + tau0) * 192 + bn] = g0;
    d_G[(size_t)(uoff + tau1) * 192 + bn] = g1;
  }
}

// K6a: partial output GEMM. Block = (t-chunk 64, b, j-segment 96).
// Thread computes 4t x 4d register tile. Partials to d_P.
__global__ void __launch_bounds__(256) k_outp(const float* __restrict__ inp, const float* __restrict__ mw) {
  __shared__ float fs[96 * 64];   // [jj][d]
  __shared__ float gs[96 * 64];   // [jj][t]
  int tc = blockIdx.x, b = blockIdx.y, js = blockIdx.z;
  int t0 = tc * 64, j0 = js * 96;
  int tid = threadIdx.x;
  float w0 = mw[0], w1 = mw[1], w2 = mw[2];
  // stage inputs slice [96 j x 64 d]
  {
    const float4* src = (const float4*)(inp + ((size_t)b * 768 + j0) * 64);
    float4* dst = (float4*)fs;
    for (int e = tid; e < 1536; e += 256) dst[e] = src[e];
  }
  // stage combined-G tile [96 j x 64 t]
  for (int e = tid; e < 6144; e += 256) {
    int jj = e >> 6, tl = e & 63;
    int jg = j0 + jj, t = t0 + tl;
    float v = w2 * d_G[(size_t)(576 + jg) * 192 + t];
    if (jg >= 384) v += w1 * d_G[(size_t)(192 + jg - 384) * 192 + t];
    if (jg >= 576) v += w0 * d_G[(size_t)(jg - 576) * 192 + t];
    gs[e] = v;
  }
  __syncthreads();
  int tg = tid >> 4, dg = tid & 15;  // 16 t-groups of 4t, 16 d-groups of 4d
  float4 a0 = make_float4(0.f,0.f,0.f,0.f), a1 = a0, a2 = a0, a3 = a0;
#pragma unroll 4
  for (int jj = 0; jj < 96; jj++) {
    float4 f = *(const float4*)&fs[jj * 64 + dg * 4];
    float4 g = *(const float4*)&gs[jj * 64 + tg * 4];
    a0.x += f.x * g.x; a0.y += f.y * g.x; a0.z += f.z * g.x; a0.w += f.w * g.x;
    a1.x += f.x * g.y; a1.y += f.y * g.y; a1.z += f.z * g.y; a1.w += f.w * g.y;
    a2.x += f.x * g.z; a2.y += f.y * g.z; a2.z += f.z * g.z; a2.w += f.w * g.z;
    a3.x += f.x * g.w; a3.y += f.y * g.w; a3.z += f.z * g.w; a3.w += f.w * g.w;
  }
  float* P = d_P + (size_t)js * 98304 + ((size_t)b * 192 + t0 + tg * 4) * 64 + dg * 4;
  *(float4*)P = a0;
  *(float4*)(P + 64) = a1;
  *(float4*)(P + 128) = a2;
  *(float4*)(P + 192) = a3;
}

// K6b: reduce 8 partials + bias
__global__ void k_red(const float* __restrict__ mb, float* __restrict__ out) {
  int idx = blockIdx.x * 256 + threadIdx.x;
  if (idx >= 98304) return;
  float s = mb[0];
#pragma unroll
  for (int j = 0; j < 8; j++) s += d_P[(size_t)j * 98304 + idx];
  out[idx] = s;
}

extern "C" void kernel_launch(void* const* d_in, const int* in_sizes, int n_in,
                              void* d_out, int out_size) {
  const float* inputs = (const float*)d_in[0];
  const float* spec_wr = (const float*)d_in[1];
  const float* spec_wi = (const float*)d_in[2];
  const float* mlp_w = (const float*)d_in[3];
  const float* mlp_b = (const float*)d_in[4];
  float* out = (float*)d_out;

  k_copy<<<256, 256>>>(h_al, (const uint4*)h_HfH, (const uint4*)h_HfL,
                       (const uint4*)h_EfH, (const uint4*)h_EfL);
  k_w2<<<dim3(256, 3), 256>>>(spec_wr, spec_wi);
  k_gemmU<<<dim3(192, 7), 384>>>();
  k_outp<<<dim3(3, 8, 8), 256>>>(inputs, mlp_w);
  k_red<<<384, 256>>>(mlp_b, out);
}

// round 17
// speedup vs baseline: 1.2941x; 1.2941x over previous
#include <cuda_runtime.h>
#include <cuda_bf16.h>
#include <vector>
#include <cmath>
#include <cstring>

#define HID 256
#define OLEN 192
#define NMODE 32
#define TSUM 1344
#define NCOL 12288   // 192*32*2
#define NH4 (84 * 16 * 32)      // H-frag uint4 count
#define NE4 (3 * 12 * 16 * 32)  // em-frag uint4 count

// ---------------- host constant tables ----------------
static float h_H[TSUM * HID];
static float h_em[3 * OLEN * HID];
static float h_al[3 * NMODE * 2];
static unsigned h_HfH[NH4 * 4], h_HfL[NH4 * 4];
static unsigned h_EfH[NE4 * 4], h_EfL[NE4 * 4];

static inline unsigned short f2bf(float x) {
  unsigned u; memcpy(&u, &x, 4);
  return (unsigned short)((u + 0x7FFF + ((u >> 16) & 1)) >> 16);
}
static inline float bff(unsigned short b) {
  unsigned u = (unsigned)b << 16; float f; memcpy(&f, &u, 4); return f;
}
static inline void pack_pair(float e0, float e1, unsigned& hi, unsigned& lo) {
  unsigned short h0 = f2bf(e0), h1 = f2bf(e1);
  unsigned short l0 = f2bf(e0 - bff(h0)), l1 = f2bf(e1 - bff(h1));
  hi = ((unsigned)h1 << 16) | h0;
  lo = ((unsigned)l1 << 16) | l0;
}

struct HostInit {
  HostInit() {
    const double PI2 = 6.283185307179586476925286766559;
    for (int si = 0; si < 3; si++) {
      int sc = 1 << si;
      int T = OLEN * sc;
      int uoff = (si == 0) ? 0 : (si == 1) ? 192 : 576;
      double dt = 1.0 / (double)T;
      std::vector<double> M((size_t)HID * HID), R((size_t)HID * (HID + 1)), X((size_t)HID * (HID + 1));
      for (int r = 0; r < HID; r++) {
        for (int c = 0; c < HID; c++) {
          double a = (r < c) ? -1.0 : (((r - c) & 1) ? 1.0 : -1.0);
          a *= (2.0 * r + 1.0);
          M[(size_t)r * HID + c] = (r == c ? 1.0 : 0.0) - 0.5 * dt * a;
          R[(size_t)r * (HID + 1) + c] = (r == c ? 1.0 : 0.0) + 0.5 * dt * a;
        }
        R[(size_t)r * (HID + 1) + HID] = ((r & 1) ? -1.0 : 1.0) * (2.0 * r + 1.0) * dt;
      }
      for (int col = 0; col < HID; col++) {
        int piv = col; double mx = fabs(M[(size_t)col * HID + col]);
        for (int r = col + 1; r < HID; r++) { double v = fabs(M[(size_t)r * HID + col]); if (v > mx) { mx = v; piv = r; } }
        if (piv != col) {
          for (int c = col; c < HID; c++) { double t = M[(size_t)col*HID+c]; M[(size_t)col*HID+c] = M[(size_t)piv*HID+c]; M[(size_t)piv*HID+c] = t; }
          for (int c = 0; c <= HID; c++) { double t = R[(size_t)col*(HID+1)+c]; R[(size_t)col*(HID+1)+c] = R[(size_t)piv*(HID+1)+c]; R[(size_t)piv*(HID+1)+c] = t; }
        }
        double d = M[(size_t)col * HID + col];
        for (int r = col + 1; r < HID; r++) {
          double f = M[(size_t)r * HID + col] / d;
          if (f != 0.0) {
            for (int c = col; c < HID; c++) M[(size_t)r*HID+c] -= f * M[(size_t)col*HID+c];
            for (int c = 0; c <= HID; c++) R[(size_t)r*(HID+1)+c] -= f * R[(size_t)col*(HID+1)+c];
          }
        }
      }
      for (int r = HID - 1; r >= 0; r--) {
        double diag = M[(size_t)r * HID + r];
        for (int c = 0; c <= HID; c++) {
          double s = R[(size_t)r * (HID + 1) + c];
          for (int rr = r + 1; rr < HID; rr++) s -= M[(size_t)r*HID+rr] * X[(size_t)rr*(HID+1)+c];
          X[(size_t)r * (HID + 1) + c] = s / diag;
        }
      }
      std::vector<double> Ad((size_t)HID * HID), h(HID), hn(HID);
      for (int r = 0; r < HID; r++) {
        for (int c = 0; c < HID; c++) Ad[(size_t)r*HID+c] = (double)(float)X[(size_t)r*(HID+1)+c];
        h[r] = (double)(float)X[(size_t)r*(HID+1)+HID];
      }
      for (int u = 0; u < T; u++) {
        for (int i = 0; i < HID; i++) h_H[(size_t)(uoff + u) * HID + i] = (float)h[i];
        for (int i = 0; i < HID; i++) {
          double s = 0; const double* row = &Ad[(size_t)i * HID];
          for (int j = 0; j < HID; j++) s += row[j] * h[j];
          hn[i] = s;
        }
        h.swap(hn);
      }
      for (int t = 0; t < OLEN; t++) {
        int j = T - OLEN + t;
        double x = 1.0 - 2.0 * ((double)j * dt);
        float* dst = &h_em[((size_t)si * OLEN + t) * HID];
        double p0 = 1.0, p1 = x;
        dst[0] = (float)p0; dst[1] = (float)p1;
        for (int n = 1; n < HID - 1; n++) {
          double p2 = ((2.0*n+1.0)*x*p1 - (double)n*p0) / (double)(n+1);
          dst[n+1] = (float)p2; p0 = p1; p1 = p2;
        }
      }
      h_al[(si * NMODE + 0) * 2 + 0] = (float)(1.0 / (double)T);
      h_al[(si * NMODE + 0) * 2 + 1] = 0.0f;
      for (int k = 1; k < NMODE; k++) {
        double th = PI2 * (double)(191 * k) / (double)T;
        h_al[(si * NMODE + k) * 2 + 0] = (float)(2.0 / T * cos(th));
        h_al[(si * NMODE + k) * 2 + 1] = (float)(2.0 / T * sin(th));
      }
    }
    for (int ut = 0; ut < 84; ut++)
      for (int mmg = 0; mmg < 16; mmg++)
        for (int lane = 0; lane < 32; lane++) {
          int r = lane >> 2, c = lane & 3;
          int r0 = ut * 16 + r, r1 = r0 + 8, i0 = mmg * 16;
          int idx = (((ut * 16) + mmg) * 32 + lane) * 4;
          pack_pair(h_H[(size_t)r0*256 + i0+2*c],   h_H[(size_t)r0*256 + i0+2*c+1], h_HfH[idx+0], h_HfL[idx+0]);
          pack_pair(h_H[(size_t)r1*256 + i0+2*c],   h_H[(size_t)r1*256 + i0+2*c+1], h_HfH[idx+1], h_HfL[idx+1]);
          pack_pair(h_H[(size_t)r0*256 + i0+2*c+8], h_H[(size_t)r0*256 + i0+2*c+9], h_HfH[idx+2], h_HfL[idx+2]);
          pack_pair(h_H[(size_t)r1*256 + i0+2*c+8], h_H[(size_t)r1*256 + i0+2*c+9], h_HfH[idx+3], h_HfL[idx+3]);
        }
    for (int s = 0; s < 3; s++)
      for (int mt = 0; mt < 12; mt++)
        for (int mmg = 0; mmg < 16; mmg++)
          for (int lane = 0; lane < 32; lane++) {
            int r = lane >> 2, c = lane & 3;
            int r0 = mt * 16 + r, r1 = r0 + 8, o0 = mmg * 16;
            const float* A = h_em + (size_t)s * 192 * 256;
            int idx = ((((s * 12 + mt) * 16) + mmg) * 32 + lane) * 4;
            pack_pair(A[(size_t)r0*256 + o0+2*c],   A[(size_t)r0*256 + o0+2*c+1], h_EfH[idx+0], h_EfL[idx+0]);
            pack_pair(A[(size_t)r1*256 + o0+2*c],   A[(size_t)r1*256 + o0+2*c+1], h_EfH[idx+1], h_EfL[idx+1]);
            pack_pair(A[(size_t)r0*256 + o0+2*c+8], A[(size_t)r0*256 + o0+2*c+9], h_EfH[idx+2], h_EfL[idx+2]);
            pack_pair(A[(size_t)r1*256 + o0+2*c+8], A[(size_t)r1*256 + o0+2*c+9], h_EfH[idx+3], h_EfL[idx+3]);
          }
  }
};
static HostInit g_init;

// ---------------- device scratch ----------------
__device__ uint4 d_HfH[NH4], d_HfL[NH4];
__device__ uint4 d_EfH[NE4], d_EfL[NE4];
__device__ __nv_bfloat16 d_W2h[3 * 256 * NCOL];
__device__ __nv_bfloat16 d_W2l[3 * 256 * NCOL];
__device__ float d_Bs[7 * 192 * 32 * 2];
__device__ int d_flag[7 * 192];
__device__ float d_G[TSUM * 192];
__device__ float d_ald[3 * 32 * 2];

__device__ __forceinline__ void mma16(float4& d, const uint4& a, unsigned b0, unsigned b1) {
  asm("mma.sync.aligned.m16n8k16.row.col.f32.bf16.bf16.f32 "
      "{%0,%1,%2,%3},{%4,%5,%6,%7},{%8,%9},{%0,%1,%2,%3};"
      : "+f"(d.x), "+f"(d.y), "+f"(d.z), "+f"(d.w)
      : "r"(a.x), "r"(a.y), "r"(a.z), "r"(a.w), "r"(b0), "r"(b1));
}

__device__ __forceinline__ unsigned pkbf(float a, float b) {
  __nv_bfloat16 ha = __float2bfloat16_rn(a), hb = __float2bfloat16_rn(b);
  return ((unsigned)__bfloat16_as_ushort(hb) << 16) | __bfloat16_as_ushort(ha);
}

__device__ __forceinline__ float scan_r(float v, int r) {
  float t;
  t = __shfl_up_sync(0xffffffffu, v, 4);  v += (r >= 1) ? t : 0.f;
  t = __shfl_up_sync(0xffffffffu, v, 8);  v += (r >= 2) ? t : 0.f;
  t = __shfl_up_sync(0xffffffffu, v, 16); v += (r >= 4) ? t : 0.f;
  return v;
}

// K0: pull host constants via ATS (GB300 C2C); zero lookback flags
__global__ void k_copy(const float* __restrict__ hal,
                       const uint4* __restrict__ hHfH, const uint4* __restrict__ hHfL,
                       const uint4* __restrict__ hEfH, const uint4* __restrict__ hEfL) {
  int i = blockIdx.x * blockDim.x + threadIdx.x, st = gridDim.x * blockDim.x;
  for (int j = i; j < 7 * 192; j += st) d_flag[j] = 0;
  for (int j = i; j < 3 * 32 * 2; j += st) d_ald[j] = hal[j];
  for (int j = i; j < NH4; j += st) { d_HfH[j] = hHfH[j]; d_HfL[j] = hHfL[j]; }
  for (int j = i; j < NE4; j += st) { d_EfH[j] = hEfH[j]; d_EfL[j] = hEfL[j]; }
}

// K1: W2 = alpha .* (em @ Wc). bf16 3-pass, double-buffered, 2 blocks/SM.
__global__ void __launch_bounds__(256, 2) k_w2(const float* __restrict__ wr, const float* __restrict__ wi) {
  __shared__ unsigned Bph[2][16 * 72], Bpl[2][16 * 72];
  int s = blockIdx.y, i = blockIdx.x;
  int tid = threadIdx.x, wid = tid >> 5, lane = tid & 31;
  int whalf = wid & 1, wg = wid >> 1;
  int r = lane >> 2, c = lane & 3;
  const float* wrb = wr + (size_t)(s * 256 + i) * 8192;
  const float* wib = wi + (size_t)(s * 256 + i) * 8192;
  float4 acc[3][4];
#pragma unroll
  for (int mt = 0; mt < 3; mt++)
#pragma unroll
    for (int j = 0; j < 4; j++) acc[mt][j] = make_float4(0.f, 0.f, 0.f, 0.f);
  int o2s = tid >> 4, kp = tid & 15;

  float2 ra, rb, ia, ib;
  {
    int oa = 2 * o2s;
    ra = *(const float2*)(wrb + (size_t)oa * 32 + 2 * kp);
    rb = *(const float2*)(wrb + (size_t)(oa + 1) * 32 + 2 * kp);
    ia = *(const float2*)(wib + (size_t)oa * 32 + 2 * kp);
    ib = *(const float2*)(wib + (size_t)(oa + 1) * 32 + 2 * kp);
  }
  for (int ch = 0; ch < 8; ch++) {
    int bsel = ch & 1;
    {
      float va[4] = {ra.x, ia.x, ra.y, ia.y};
      float vb[4] = {rb.x, ib.x, rb.y, ib.y};
#pragma unroll
      for (int e = 0; e < 4; e++) {
        int n = 4 * kp + e;
        int p = o2s * 72 + (n & 7) * 8 + (n >> 3);
        __nv_bfloat16 ha = __float2bfloat16_rn(va[e]), hb = __float2bfloat16_rn(vb[e]);
        Bph[bsel][p] = ((unsigned)__bfloat16_as_ushort(hb) << 16) | __bfloat16_as_ushort(ha);
        Bpl[bsel][p] = pkbf(va[e] - __bfloat162float(ha), vb[e] - __bfloat162float(hb));
      }
    }
    __syncthreads();
    if (ch < 7) {
      int oa = (ch + 1) * 32 + 2 * o2s;
      ra = *(const float2*)(wrb + (size_t)oa * 32 + 2 * kp);
      rb = *(const float2*)(wrb + (size_t)(oa + 1) * 32 + 2 * kp);
      ia = *(const float2*)(wib + (size_t)oa * 32 + 2 * kp);
      ib = *(const float2*)(wib + (size_t)(oa + 1) * 32 + 2 * kp);
    }
#pragma unroll
    for (int m = 0; m < 2; m++) {
      uint4 b0h = *(const uint4*)&Bph[bsel][(8 * m + c) * 72 + r * 8 + whalf * 4];
      uint4 b1h = *(const uint4*)&Bph[bsel][(8 * m + c + 4) * 72 + r * 8 + whalf * 4];
      uint4 b0l = *(const uint4*)&Bpl[bsel][(8 * m + c) * 72 + r * 8 + whalf * 4];
      uint4 b1l = *(const uint4*)&Bpl[bsel][(8 * m + c + 4) * 72 + r * 8 + whalf * 4];
      const unsigned* p0h = (const unsigned*)&b0h;
      const unsigned* p1h = (const unsigned*)&b1h;
      const unsigned* p0l = (const unsigned*)&b0l;
      const unsigned* p1l = (const unsigned*)&b1l;
      int mmg = ch * 2 + m;
#pragma unroll
      for (int mt = 0; mt < 3; mt++) {
        int mtile = wg * 3 + mt;
        uint4 ah = d_EfH[((s * 12 + mtile) * 16 + mmg) * 32 + lane];
        uint4 al = d_EfL[((s * 12 + mtile) * 16 + mmg) * 32 + lane];
#pragma unroll
        for (int j = 0; j < 4; j++) {
          mma16(acc[mt][j], ah, p0h[j], p1h[j]);
          mma16(acc[mt][j], ah, p0l[j], p1l[j]);
          mma16(acc[mt][j], al, p0h[j], p1h[j]);
        }
      }
    }
  }
  size_t base0 = (size_t)(s * 256 + i) * NCOL;
#pragma unroll
  for (int mt = 0; mt < 3; mt++) {
#pragma unroll
    for (int j = 0; j < 4; j++) {
      int ncol = whalf * 32 + j * 8 + 2 * c;
      int kmode = ncol >> 1;
      float alr = d_ald[(s * 32 + kmode) * 2], ali = d_ald[(s * 32 + kmode) * 2 + 1];
      float4 cv = acc[mt][j];
      int t0 = wg * 48 + mt * 16 + r;
      float re0 = alr * cv.x - ali * cv.y, im0 = alr * cv.y + ali * cv.x;
      float re1 = alr * cv.z - ali * cv.w, im1 = alr * cv.w + ali * cv.z;
      size_t e0 = base0 + (size_t)t0 * 64 + ncol;
      size_t e1 = base0 + (size_t)(t0 + 8) * 64 + ncol;
      __nv_bfloat16 h0r = __float2bfloat16_rn(re0), h0i = __float2bfloat16_rn(im0);
      __nv_bfloat16 h1r = __float2bfloat16_rn(re1), h1i = __float2bfloat16_rn(im1);
      *(unsigned*)(d_W2h + e0) = ((unsigned)__bfloat16_as_ushort(h0i) << 16) | __bfloat16_as_ushort(h0r);
      *(unsigned*)(d_W2h + e1) = ((unsigned)__bfloat16_as_ushort(h1i) << 16) | __bfloat16_as_ushort(h1r);
      *(unsigned*)(d_W2l + e0) = pkbf(re0 - __bfloat162float(h0r), im0 - __bfloat162float(h0i));
      *(unsigned*)(d_W2l + e1) = pkbf(re1 - __bfloat162float(h1r), im1 - __bfloat162float(h1i));
    }
  }
}

// K2: fused GEMM + scan + k-reduction with cross-chunk lookback (2 blocks/SM).
__global__ void __launch_bounds__(384, 2) k_gemmU() {
  __shared__ unsigned Bph[2][16 * 72], Bpl[2][16 * 72];
  __shared__ float WsRe[12][32], WsIm[12][32];
  int bn = blockIdx.x, ub = blockIdx.y;
  int s = (ub == 0) ? 0 : (ub < 3) ? 1 : 2;
  int tid = threadIdx.x, wid = tid >> 5, lane = tid & 31;
  int r = lane >> 2, c = lane & 3;
  int ut = ub * 12 + wid;
  float4 acc[8];
#pragma unroll
  for (int j = 0; j < 8; j++) acc[j] = make_float4(0.f, 0.f, 0.f, 0.f);

  int pairsel = tid >> 7, t2 = tid & 127;
  int k2 = t2 >> 3, oc = t2 & 7;
  const __nv_bfloat16* bbase = pairsel ? d_W2l : d_W2h;
  uint4 va, vb;
  if (tid < 256) {
    const __nv_bfloat16* src = bbase + (size_t)(s * 256 + 2 * k2) * NCOL + bn * 64 + oc * 8;
    va = *(const uint4*)src;
    vb = *(const uint4*)(src + NCOL);
  }
  for (int ch = 0; ch < 8; ch++) {
    int bsel = ch & 1;
    if (tid < 256) {
      unsigned* dst = pairsel ? Bpl[bsel] : Bph[bsel];
      const unsigned* pa = (const unsigned*)&va;
      const unsigned* pb = (const unsigned*)&vb;
#pragma unroll
      for (int h2 = 0; h2 < 4; h2++) {
        int n0 = oc * 8 + h2 * 2, n1 = n0 + 1;
        dst[k2 * 72 + (n0 & 7) * 8 + (n0 >> 3)] = __byte_perm(pa[h2], pb[h2], 0x5410);
        dst[k2 * 72 + (n1 & 7) * 8 + (n1 >> 3)] = __byte_perm(pa[h2], pb[h2], 0x7632);
      }
    }
    __syncthreads();
    if (ch < 7 && tid < 256) {
      const __nv_bfloat16* src = bbase + (size_t)(s * 256 + (ch + 1) * 32 + 2 * k2) * NCOL + bn * 64 + oc * 8;
      va = *(const uint4*)src;
      vb = *(const uint4*)(src + NCOL);
    }
#pragma unroll
    for (int m = 0; m < 2; m++) {
      int mmg = ch * 2 + m;
      uint4 ah = d_HfH[(ut * 16 + mmg) * 32 + lane];
      uint4 al = d_HfL[(ut * 16 + mmg) * 32 + lane];
#pragma unroll
      for (int half = 0; half < 2; half++) {
        uint4 b0h = *(const uint4*)&Bph[bsel][(8 * m + c) * 72 + r * 8 + half * 4];
        uint4 b1h = *(const uint4*)&Bph[bsel][(8 * m + c + 4) * 72 + r * 8 + half * 4];
        uint4 b0l = *(const uint4*)&Bpl[bsel][(8 * m + c) * 72 + r * 8 + half * 4];
        uint4 b1l = *(const uint4*)&Bpl[bsel][(8 * m + c + 4) * 72 + r * 8 + half * 4];
        const unsigned* p0h = (const unsigned*)&b0h;
        const unsigned* p1h = (const unsigned*)&b1h;
        const unsigned* p0l = (const unsigned*)&b0l;
        const unsigned* p1l = (const unsigned*)&b1l;
#pragma unroll
        for (int j = 0; j < 4; j++) {
          int jj = half * 4 + j;
          mma16(acc[jj], ah, p0h[j], p1h[j]);
          mma16(acc[jj], ah, p0l[j], p1l[j]);
          mma16(acc[jj], al, p0h[j], p1h[j]);
        }
      }
    }
  }
  // ---------- fused scan epilogue (angle-addition recurrence) ----------
  int T = 192 << s;
  int uoff = (s == 0) ? 0 : (s == 1) ? 192 : 576;
  int ul0 = ub * 192 - uoff + wid * 16;
  float pi2t = 6.2831853071795864f / (float)T;
  int u0 = ul0 + r, u1 = u0 + 8;
  float cu0, su0, cu1, su1, cs0, ss0, cs1, ss1;
  __sincosf(pi2t * (float)((u0 * c) % T), &su0, &cu0);
  __sincosf(pi2t * (float)((u1 * c) % T), &su1, &cu1);
  __sincosf(pi2t * (float)((4 * u0) % T), &ss0, &cs0);
  __sincosf(pi2t * (float)((4 * u1) % T), &ss1, &cs1);
#pragma unroll
  for (int j = 0; j < 8; j++) {
    float re0 = cu0 * acc[j].x + su0 * acc[j].y;
    float im0 = cu0 * acc[j].y - su0 * acc[j].x;
    float re1 = cu1 * acc[j].z + su1 * acc[j].w;
    float im1 = cu1 * acc[j].w - su1 * acc[j].z;
    acc[j].x = re0; acc[j].y = im0; acc[j].z = re1; acc[j].w = im1;
    float t0 = cu0 * cs0 - su0 * ss0; su0 = su0 * cs0 + cu0 * ss0; cu0 = t0;
    float t1 = cu1 * cs1 - su1 * ss1; su1 = su1 * cs1 + cu1 * ss1; cu1 = t1;
  }
#pragma unroll
  for (int j = 0; j < 8; j++) {
    acc[j].x = scan_r(acc[j].x, r);
    acc[j].y = scan_r(acc[j].y, r);
    float t0re = __shfl_sync(0xffffffffu, acc[j].x, 28 + c);
    float t0im = __shfl_sync(0xffffffffu, acc[j].y, 28 + c);
    acc[j].z = scan_r(acc[j].z, r) + t0re;
    acc[j].w = scan_r(acc[j].w, r) + t0im;
  }
  if (r == 7) {
#pragma unroll
    for (int j = 0; j < 8; j++) { WsRe[wid][j * 4 + c] = acc[j].z; WsIm[wid][j * 4 + c] = acc[j].w; }
  }
  __syncthreads();
  if (wid == 0) {
    float runr = 0.f, runi = 0.f;
#pragma unroll
    for (int w = 0; w < 12; w++) {
      float tr = WsRe[w][lane], ti = WsIm[w][lane];
      WsRe[w][lane] = runr; WsIm[w][lane] = runi;
      runr += tr; runi += ti;
    }
    ((float2*)d_Bs)[(ub * 192 + bn) * 32 + lane] = make_float2(runr, runi);
    __threadfence();
    __syncwarp();
    if (lane == 0) atomicExch(&d_flag[ub * 192 + bn], 1);
    int ubbase = (s == 0) ? 0 : (s == 1) ? 1 : 3;
    if (ub > ubbase) {
      float sr = 0.f, si = 0.f;
      for (int p = ubbase; p < ub; p++) {
        if (lane == 0) { while (atomicAdd(&d_flag[p * 192 + bn], 0) == 0) {} }
        __syncwarp();
        __threadfence();
        float2 v = ((const float2*)d_Bs)[(p * 192 + bn) * 32 + lane];
        sr += v.x; si += v.y;
      }
#pragma unroll
      for (int w = 0; w < 12; w++) { WsRe[w][lane] += sr; WsIm[w][lane] += si; }
    }
  }
  __syncthreads();
  int m0 = ul0 + r, m1 = m0 + 8;
  int tau0 = T - 1 - m0, tau1 = T - 1 - m1;
  float ca0, sa0, ca1, sa1, cS0, sS0, cS1, sS1;
  __sincosf(pi2t * (float)((tau0 * c) % T), &sa0, &ca0);
  __sincosf(pi2t * (float)((tau1 * c) % T), &sa1, &ca1);
  __sincosf(pi2t * (float)((4 * tau0) % T), &sS0, &cS0);
  __sincosf(pi2t * (float)((4 * tau1) % T), &sS1, &cS1);
  float g0 = 0.f, g1 = 0.f;
#pragma unroll
  for (int j = 0; j < 8; j++) {
    int k = j * 4 + c;
    float wre = WsRe[wid][k], wim = WsIm[wid][k];
    float pre0 = acc[j].x + wre, pim0 = acc[j].y + wim;
    float pre1 = acc[j].z + wre, pim1 = acc[j].w + wim;
    g0 += ca0 * pre0 + sa0 * pim0;
    g1 += ca1 * pre1 + sa1 * pim1;
    float t0 = ca0 * cS0 - sa0 * sS0; sa0 = sa0 * cS0 + ca0 * sS0; ca0 = t0;
    float t1 = ca1 * cS1 - sa1 * sS1; sa1 = sa1 * cS1 + ca1 * sS1; ca1 = t1;
  }
  g0 += __shfl_xor_sync(0xffffffffu, g0, 1);
  g0 += __shfl_xor_sync(0xffffffffu, g0, 2);
  g1 += __shfl_xor_sync(0xffffffffu, g1, 1);
  g1 += __shfl_xor_sync(0xffffffffu, g1, 2);
  if (c == 0) {
    d_G[(size_t)(uoff + tau0) * 192 + bn] = g0;
    d_G[(size_t)(uoff + tau1) * 192 + bn] = g1;
  }
}

// K6: out[b,t,d] = mlp_b + sum_j inputs[b,j,d] * Gc[j,t]
// Grid (12 t-chunks x 8 b), 512 threads: 2 j-halves of 256, in-block reduce.
__global__ void __launch_bounds__(512) k_out(const float* __restrict__ inp, const float* __restrict__ mw,
                      const float* __restrict__ mb, float* __restrict__ out) {
  __shared__ float fs[2][2][4096];
  __shared__ float gs[2][2][1024];
  __shared__ float4 red[256];
  int b = blockIdx.y, tt = blockIdx.x;  // tt in [0,12)
  int t0 = tt * 16;
  int tid = threadIdx.x;
  int half = tid >> 8, lt = tid & 255;
  int tq = lt >> 4, dg = lt & 15;
  const float* ib = inp + (size_t)b * 768 * 64;
  float w0 = mw[0], w1 = mw[1], w2 = mw[2];
  float4 pf[4];
  float pg[4];
  {
    int j0 = half * 384;
    const float4* src = (const float4*)(ib + (size_t)j0 * 64) + lt * 4;
#pragma unroll
    for (int q = 0; q < 4; q++) pf[q] = src[q];
#pragma unroll
    for (int q = 0; q < 4; q++) {
      int idx = lt * 4 + q;
      int jj = idx >> 4, tl = idx & 15;
      int jg = j0 + jj;
      int t = t0 + tl;
      float v = w2 * d_G[(size_t)(576 + jg) * 192 + t];
      if (jg >= 384) v += w1 * d_G[(size_t)(192 + jg - 384) * 192 + t];
      if (jg >= 576) v += w0 * d_G[(size_t)(jg - 576) * 192 + t];
      pg[q] = v;
    }
  }
  float4 acc = make_float4(0.f, 0.f, 0.f, 0.f);
  for (int ch = 0; ch < 6; ch++) {
    int bsel = ch & 1;
    {
      float4* dst = (float4*)fs[bsel][half] + lt * 4;
#pragma unroll
      for (int q = 0; q < 4; q++) dst[q] = pf[q];
#pragma unroll
      for (int q = 0; q < 4; q++) gs[bsel][half][lt * 4 + q] = pg[q];
    }
    __syncthreads();
    if (ch < 5) {
      int j0 = (half * 6 + ch + 1) * 64;
      const float4* src = (const float4*)(ib + (size_t)j0 * 64) + lt * 4;
#pragma unroll
      for (int q = 0; q < 4; q++) pf[q] = src[q];
#pragma unroll
      for (int q = 0; q < 4; q++) {
        int idx = lt * 4 + q;
        int jj = idx >> 4, tl = idx & 15;
        int jg = j0 + jj;
        int t = t0 + tl;
        float v = w2 * d_G[(size_t)(576 + jg) * 192 + t];
        if (jg >= 384) v += w1 * d_G[(size_t)(192 + jg - 384) * 192 + t];
        if (jg >= 576) v += w0 * d_G[(size_t)(jg - 576) * 192 + t];
        pg[q] = v;
      }
    }
#pragma unroll 8
    for (int jj = 0; jj < 64; jj++) {
      float4 f = *(const float4*)&fs[bsel][half][jj * 64 + dg * 4];
      float g = gs[bsel][half][jj * 16 + tq];
      acc.x += f.x * g; acc.y += f.y * g; acc.z += f.z * g; acc.w += f.w * g;
    }
    __syncthreads();
  }
  if (half == 1) red[lt] = acc;
  __syncthreads();
  if (half == 0) {
    float4 o = red[lt];
    float bb = mb[0];
    acc.x += o.x + bb; acc.y += o.y + bb; acc.z += o.z + bb; acc.w += o.w + bb;
    int t = t0 + tq;
    *(float4*)(out + ((size_t)b * 192 + t) * 64 + dg * 4) = acc;
  }
}

extern "C" void kernel_launch(void* const* d_in, const int* in_sizes, int n_in,
                              void* d_out, int out_size) {
  const float* inputs = (const float*)d_in[0];
  const float* spec_wr = (const float*)d_in[1];
  const float* spec_wi = (const float*)d_in[2];
  const float* mlp_w = (const float*)d_in[3];
  const float* mlp_b = (const float*)d_in[4];
  float* out = (float*)d_out;

  k_copy<<<256, 256>>>(h_al, (const uint4*)h_HfH, (const uint4*)h_HfL,
                       (const uint4*)h_EfH, (const uint4*)h_EfL);
  k_w2<<<dim3(256, 3), 256>>>(spec_wr, spec_wi);
  k_gemmU<<<dim3(192, 7), 384>>>();
  k_out<<<dim3(12, 8), 512>>>(inputs, mlp_w, mlp_b, out);
}